// round 13
// baseline (speedup 1.0000x reference)
#include <cuda_runtime.h>
#include <cuda_fp16.h>
#include <math.h>
#include <stdint.h>

#define NROWS 16384
#define DK    2048
#define DOUT  2048

// GEMM tiling: 128x64 CTA tile, 8 warps of 32x32, k32 stages, 5-stage ring
#define BM 128
#define BN 64
#define NST 5
#define ATILE_B (BM * 64)      // 8192 B  (128 rows x 32 fp16 = 64B rows)
#define WTILE_B (BN * 64)      // 4096 B
#define STAGE_B (ATILE_B + 2 * WTILE_B)   // 16384
#define SMEM_BYTES_G (NST * STAGE_B)      // 81920
#define NSTAGES_K (DK / 32)    // 64

// ---------------- device scratch (no allocations allowed) ----------------
__device__ float g_psum[512][DK];
__device__ float g_psq [512][DK];
__device__ float g_scale[DK];
__device__ float g_shift[DK];
__device__ float g_c1[DOUT];            // folded: b1_j + dot(shift, W1_j)
__device__ float g_c2[DOUT];            // folded: b2_j + dot(shift, W2_j)

__device__ uint4 g_Ah [(size_t)NROWS * DK / 8];   // fp16 raw x, 64 MB
__device__ uint4 g_W1h[(size_t)DOUT * DK / 8];    // fp16 scaled weights, 8 MB each
__device__ uint4 g_W2h[(size_t)DOUT * DK / 8];

// ---------------- helpers ----------------
__device__ __forceinline__ uint32_t smem_u32(const void* p) {
    uint32_t a;
    asm("{ .reg .u64 t; cvta.to.shared.u64 t, %1; cvt.u32.u64 %0, t; }" : "=r"(a) : "l"(p));
    return a;
}
#define CP16(dst, src) \
    asm volatile("cp.async.cg.shared.global [%0], [%1], 16;" :: "r"(dst), "l"(src))
#define CP_COMMIT() asm volatile("cp.async.commit_group;" ::: "memory")
#define CP_WAIT3()  asm volatile("cp.async.wait_group 3;" ::: "memory")
#define CP_WAIT0()  asm volatile("cp.async.wait_group 0;" ::: "memory")

// swizzled offset inside a tile with 64B rows: 16B chunk XOR'ed by row bits
__device__ __forceinline__ uint32_t swz(int row, int c) {
    return (uint32_t)(row * 64 + ((c ^ ((row >> 1) & 3)) << 4));
}

__device__ __forceinline__ void ldsm4(uint32_t* r, uint32_t addr) {
    asm volatile("ldmatrix.sync.aligned.m8n8.x4.shared.b16 {%0,%1,%2,%3}, [%4];"
                 : "=r"(r[0]), "=r"(r[1]), "=r"(r[2]), "=r"(r[3]) : "r"(addr));
}

__device__ __forceinline__ void mma16816(float* d, const uint32_t* a, const uint32_t* b) {
    asm volatile(
        "mma.sync.aligned.m16n8k16.row.col.f32.f16.f16.f32 "
        "{%0,%1,%2,%3}, {%4,%5,%6,%7}, {%8,%9}, {%0,%1,%2,%3};"
        : "+f"(d[0]), "+f"(d[1]), "+f"(d[2]), "+f"(d[3])
        : "r"(a[0]), "r"(a[1]), "r"(a[2]), "r"(a[3]), "r"(b[0]), "r"(b[1]));
}

// A-style ldmatrix address: mat bit0 -> +8 rows, bit1 -> +k8 chunk
__device__ __forceinline__ uint32_t addrA(uint32_t tbase, int rowbase, int c0, int lid) {
    int m = lid >> 3, r8 = lid & 7;
    int row = rowbase + r8 + (m & 1) * 8;
    int ch  = c0 + (m >> 1);
    return tbase + swz(row, ch);
}
// B-style ldmatrix address: mat bit0 -> +k8 chunk, bit1 -> +8 rows
__device__ __forceinline__ uint32_t addrB(uint32_t tbase, int rowbase, int c0, int lid) {
    int m = lid >> 3, r8 = lid & 7;
    int row = rowbase + r8 + (m >> 1) * 8;
    int ch  = c0 + (m & 1);
    return tbase + swz(row, ch);
}

__device__ __forceinline__ uint32_t pack2h(float a, float b) {
    __half2 h = __floats2half2_rn(a, b);
    return *reinterpret_cast<uint32_t*>(&h);
}

// ---------------- pass 1: column stats partials + x -> fp16 (single read of x) ----------------
// 1024 CTAs: 32-row groups x 2 column halves -> ~7 CTA/SM for MLP
__global__ void stats_and_convx(const float* __restrict__ x) {
    const int bx  = blockIdx.x;
    const int tid = threadIdx.x;
    const int by  = bx >> 1;                       // 32-row group, 0..511
    const int c4  = (bx & 1) * 256 + tid;          // float4 column, 0..511
    const float4* p = (const float4*)x + (size_t)(by * 32) * (DK / 4) + c4;
    uint2* outp = (uint2*)((char*)g_Ah + (size_t)(by * 32) * 4096 + c4 * 8);
    float4 s  = make_float4(0.f, 0.f, 0.f, 0.f);
    float4 ss = make_float4(0.f, 0.f, 0.f, 0.f);
#pragma unroll 4
    for (int r = 0; r < 32; ++r) {
        float4 v = p[(size_t)r * (DK / 4)];
        s.x += v.x; s.y += v.y; s.z += v.z; s.w += v.w;
        ss.x += v.x * v.x; ss.y += v.y * v.y;
        ss.z += v.z * v.z; ss.w += v.w * v.w;
        uint2 h;
        h.x = pack2h(v.x, v.y);
        h.y = pack2h(v.z, v.w);
        outp[(size_t)r * (DK / 4)] = h;   // fp16 row = 4096 B = 512 uint2
    }
    *(float4*)&g_psum[by][c4 * 4] = s;
    *(float4*)&g_psq [by][c4 * 4] = ss;
}

__global__ void colstats_final(const float* __restrict__ gamma,
                               const float* __restrict__ beta) {
    int col = blockIdx.x * 256 + threadIdx.x;
    float s = 0.f, ss = 0.f;
#pragma unroll 8
    for (int c = 0; c < 512; ++c) { s += g_psum[c][col]; ss += g_psq[c][col]; }
    float mean = s / (float)NROWS;
    float var  = (ss - s * mean) / (float)(NROWS - 1);   // ddof=1 (torch.std)
    float inv  = rsqrtf(var + 1e-8f);
    float sc   = gamma[col] * inv;
    g_scale[col] = sc;
    g_shift[col] = beta[col] - mean * sc;
}

// ---------------- pass 2: W*scale -> fp16, plus folded bias c_j = b_j + dot(shift, W_j) ----------------
__global__ void convert_w_scaled(const float* __restrict__ w1,
                                 const float* __restrict__ w2,
                                 const float* __restrict__ b1v,
                                 const float* __restrict__ b2v) {
    __shared__ float red[16];
    const int j   = blockIdx.x;
    const int tid = threadIdx.x;
    const int k0  = tid * 8;                       // 8 columns per thread
    const float4* wp1 = (const float4*)(w1 + (size_t)j * DK + k0);
    const float4* wp2 = (const float4*)(w2 + (size_t)j * DK + k0);
    const float4* scp = (const float4*)(g_scale + k0);
    const float4* shp = (const float4*)(g_shift + k0);
    float4 a0 = wp1[0], a1 = wp1[1];
    float4 b0 = wp2[0], b1 = wp2[1];
    float4 s0 = scp[0], s1 = scp[1];
    float4 h0 = shp[0], h1 = shp[1];

    float w1s[8] = { a0.x*s0.x, a0.y*s0.y, a0.z*s0.z, a0.w*s0.w,
                     a1.x*s1.x, a1.y*s1.y, a1.z*s1.z, a1.w*s1.w };
    float w2s[8] = { b0.x*s0.x, b0.y*s0.y, b0.z*s0.z, b0.w*s0.w,
                     b1.x*s1.x, b1.y*s1.y, b1.z*s1.z, b1.w*s1.w };
    uint4 o1, o2;
    o1.x = pack2h(w1s[0], w1s[1]); o1.y = pack2h(w1s[2], w1s[3]);
    o1.z = pack2h(w1s[4], w1s[5]); o1.w = pack2h(w1s[6], w1s[7]);
    o2.x = pack2h(w2s[0], w2s[1]); o2.y = pack2h(w2s[2], w2s[3]);
    o2.z = pack2h(w2s[4], w2s[5]); o2.w = pack2h(w2s[6], w2s[7]);
    const size_t idx = (size_t)j * (DK / 8) + tid;
    g_W1h[idx] = o1;
    g_W2h[idx] = o2;

    float d1 = h0.x*a0.x + h0.y*a0.y + h0.z*a0.z + h0.w*a0.w
             + h1.x*a1.x + h1.y*a1.y + h1.z*a1.z + h1.w*a1.w;
    float d2 = h0.x*b0.x + h0.y*b0.y + h0.z*b0.z + h0.w*b0.w
             + h1.x*b1.x + h1.y*b1.y + h1.z*b1.z + h1.w*b1.w;
#pragma unroll
    for (int o = 16; o > 0; o >>= 1) {
        d1 += __shfl_down_sync(0xFFFFFFFF, d1, o);
        d2 += __shfl_down_sync(0xFFFFFFFF, d2, o);
    }
    const int wrp = tid >> 5, lid = tid & 31;
    if (lid == 0) { red[wrp] = d1; red[wrp + 8] = d2; }
    __syncthreads();
    if (tid == 0) {
        float c1 = 0.f, c2 = 0.f;
#pragma unroll
        for (int t = 0; t < 8; ++t) { c1 += red[t]; c2 += red[t + 8]; }
        g_c1[j] = c1 + b1v[j];
        g_c2[j] = c2 + b2v[j];
    }
}

__device__ __forceinline__ float clamp_small(float t) {
    const float EPS = 1e-12f;
    if (t >= 0.f && t <  EPS) return  EPS;
    if (t <  0.f && t > -EPS) return -EPS;
    return t;
}

// ---------------- fused dual GEMM (plain fp16 mma.sync, 8 warps x 32x32) ----------------
__global__ __launch_bounds__(256, 2)
void dual_gemm_mma(float* __restrict__ out) {
    extern __shared__ __align__(128) char smem[];
    const uint32_t sbase = smem_u32(smem);

    const int tid = threadIdx.x;
    const int lid = tid & 31;
    const int wid = tid >> 5;
    const int wm  = wid & 3;        // 4 warps along M
    const int wn  = wid >> 2;       // 2 warps along N

    // rasterize: 8 n-tiles per group, m fastest -> wave shares A rows & W cols in L2
    const int id  = blockIdx.x;
    const int grp = id >> 10;
    const int rem = id & 1023;
    const int m0  = (rem >> 3) * BM;
    const int n0  = ((grp << 3) | (rem & 7)) * BN;

    const char* srcA  = (const char*)g_Ah  + (size_t)m0 * 4096;
    const char* srcW1 = (const char*)g_W1h + (size_t)n0 * 4096;
    const char* srcW2 = (const char*)g_W2h + (size_t)n0 * 4096;

    const int arow0 = tid >> 2;        // 0..63, A covers 128 rows in two passes
    const int ac    = tid & 3;

    auto issueA = [&](int bi, int kb) {
        const uint32_t st = sbase + bi * STAGE_B;
#pragma unroll
        for (int j = 0; j < 2; ++j) {
            int row = arow0 + 64 * j;
            CP16(st + swz(row, ac), srcA + (size_t)row * 4096 + kb + ac * 16);
        }
    };
    auto issueW = [&](int bi, int kb) {
        const uint32_t st = sbase + bi * STAGE_B;
        uint32_t d = st + ATILE_B + swz(arow0, ac);
        const size_t off = (size_t)arow0 * 4096 + kb + ac * 16;
        CP16(d,           srcW1 + off);
        CP16(d + WTILE_B, srcW2 + off);
    };

    float acc1[2][4][4];
    float acc2[2][4][4];
#pragma unroll
    for (int mi = 0; mi < 2; ++mi)
#pragma unroll
        for (int ni = 0; ni < 4; ++ni)
#pragma unroll
            for (int j = 0; j < 4; ++j) { acc1[mi][ni][j] = 0.f; acc2[mi][ni][j] = 0.f; }

    // prologue: 4 stages in flight
#pragma unroll
    for (int p = 0; p < 4; ++p) {
        issueA(p, p * 64);
        issueW(p, p * 64);
        CP_COMMIT();
    }

    for (int i = 0; i < NSTAGES_K; ++i) {
        CP_WAIT3();
        __syncthreads();   // orders compute(i-1) before writes into stage (i-1)%5 below
        const int   nb = (i + 4) % NST;
        const bool  pf = (i + 4 < NSTAGES_K);
        const uint32_t st  = sbase + (i % NST) * STAGE_B;
        const uint32_t stW = st + ATILE_B;

        if (pf) issueA(nb, (i + 4) * 64);

        // ---- ks = 0 ----
        {
            uint32_t ah[2][4];
            ldsm4(ah[0], addrA(st, wm * 32,      0, lid));
            ldsm4(ah[1], addrA(st, wm * 32 + 16, 0, lid));
            uint32_t w[2][8];
            ldsm4(&w[0][0], addrB(stW,           wn * 32,      0, lid));
            ldsm4(&w[0][4], addrB(stW,           wn * 32 + 16, 0, lid));
            ldsm4(&w[1][0], addrB(stW + WTILE_B, wn * 32,      0, lid));
            ldsm4(&w[1][4], addrB(stW + WTILE_B, wn * 32 + 16, 0, lid));
#pragma unroll
            for (int mi = 0; mi < 2; ++mi)
#pragma unroll
                for (int ni = 0; ni < 4; ++ni) {
                    mma16816(acc1[mi][ni], ah[mi], &w[0][ni * 2]);
                    mma16816(acc2[mi][ni], ah[mi], &w[1][ni * 2]);
                }
        }

        if (pf) issueW(nb, (i + 4) * 64);
        CP_COMMIT();

        // ---- ks = 1 ----
        {
            uint32_t ah[2][4];
            ldsm4(ah[0], addrA(st, wm * 32,      2, lid));
            ldsm4(ah[1], addrA(st, wm * 32 + 16, 2, lid));
            uint32_t w[2][8];
            ldsm4(&w[0][0], addrB(stW,           wn * 32,      2, lid));
            ldsm4(&w[0][4], addrB(stW,           wn * 32 + 16, 2, lid));
            ldsm4(&w[1][0], addrB(stW + WTILE_B, wn * 32,      2, lid));
            ldsm4(&w[1][4], addrB(stW + WTILE_B, wn * 32 + 16, 2, lid));
#pragma unroll
            for (int mi = 0; mi < 2; ++mi)
#pragma unroll
                for (int ni = 0; ni < 4; ++ni) {
                    mma16816(acc1[mi][ni], ah[mi], &w[0][ni * 2]);
                    mma16816(acc2[mi][ni], ah[mi], &w[1][ni * 2]);
                }
        }
        // no tail sync: head sync of next iteration provides the WAR ordering
    }
    CP_WAIT0();

    // epilogue: folded bias + sigmoid + clamp + product
#pragma unroll
    for (int mi = 0; mi < 2; ++mi) {
        const int mrow = m0 + wm * 32 + mi * 16 + (lid >> 2);
#pragma unroll
        for (int ni = 0; ni < 4; ++ni) {
            const int col = n0 + wn * 32 + ni * 8 + (lid & 3) * 2;
            const float b1x = g_c1[col], b1y = g_c1[col + 1];
            const float b2x = g_c2[col], b2y = g_c2[col + 1];

            float h1, z, s;
            float2 r;
            h1 = clamp_small(acc1[mi][ni][0] + b1x);
            z  = acc2[mi][ni][0] + b2x;
            s  = clamp_small(1.0f / (1.0f + __expf(-z)));
            r.x = h1 * s;
            h1 = clamp_small(acc1[mi][ni][1] + b1y);
            z  = acc2[mi][ni][1] + b2y;
            s  = clamp_small(1.0f / (1.0f + __expf(-z)));
            r.y = h1 * s;
            *(float2*)(out + (size_t)mrow * DOUT + col) = r;

            h1 = clamp_small(acc1[mi][ni][2] + b1x);
            z  = acc2[mi][ni][2] + b2x;
            s  = clamp_small(1.0f / (1.0f + __expf(-z)));
            r.x = h1 * s;
            h1 = clamp_small(acc1[mi][ni][3] + b1y);
            z  = acc2[mi][ni][3] + b2y;
            s  = clamp_small(1.0f / (1.0f + __expf(-z)));
            r.y = h1 * s;
            *(float2*)(out + (size_t)(mrow + 8) * DOUT + col) = r;
        }
    }
}

// ---------------- launch ----------------
extern "C" void kernel_launch(void* const* d_in, const int* in_sizes, int n_in,
                              void* d_out, int out_size) {
    const float* x     = (const float*)d_in[0];
    const float* w1    = (const float*)d_in[1];
    const float* b1    = (const float*)d_in[2];
    const float* w2    = (const float*)d_in[3];
    const float* b2    = (const float*)d_in[4];
    const float* gamma = (const float*)d_in[5];
    const float* beta  = (const float*)d_in[6];
    float* out = (float*)d_out;

    cudaFuncSetAttribute(dual_gemm_mma, cudaFuncAttributeMaxDynamicSharedMemorySize,
                         SMEM_BYTES_G);

    stats_and_convx<<<1024, 256>>>(x);
    colstats_final<<<DK / 256, 256>>>(gamma, beta);
    convert_w_scaled<<<DOUT, 256>>>(w1, w2, b1, b2);

    const int grid = (NROWS / BM) * (DOUT / BN);   // 4096
    dual_gemm_mma<<<grid, 256, SMEM_BYTES_G>>>(out);
}

// round 14
// speedup vs baseline: 1.0502x; 1.0502x over previous
#include <cuda_runtime.h>
#include <cuda_fp16.h>
#include <math.h>
#include <stdint.h>

#define NROWS 16384
#define DK    2048
#define DOUT  2048

// GEMM tiling: 128x64 CTA tile, 8 warps of 32x32, k32 stages, 5-stage ring
#define BM 128
#define BN 64
#define NST 5
#define ATILE_B (BM * 64)      // 8192 B  (128 rows x 32 fp16 = 64B rows)
#define WTILE_B (BN * 64)      // 4096 B
#define STAGE_B (ATILE_B + 2 * WTILE_B)   // 16384
#define RING_B  (NST * STAGE_B)           // 81920
#define SMEM_BYTES_G (RING_B + 1024)      // + c1/c2 staging
#define NSTAGES_K (DK / 32)    // 64

// ---------------- device scratch (no allocations allowed) ----------------
__device__ float g_psum[256][DK];
__device__ float g_psq [256][DK];
__device__ float g_scale[DK];
__device__ float g_shift[DK];
__device__ float g_c1[DOUT];            // folded: b1_j + dot(shift, W1_j)
__device__ float g_c2[DOUT];            // folded: b2_j + dot(shift, W2_j)

__device__ uint4 g_Ah [(size_t)NROWS * DK / 8];   // fp16 raw x, 64 MB
__device__ uint4 g_W1h[(size_t)DOUT * DK / 8];    // fp16 scaled weights, 8 MB each
__device__ uint4 g_W2h[(size_t)DOUT * DK / 8];

// ---------------- helpers ----------------
__device__ __forceinline__ uint32_t smem_u32(const void* p) {
    uint32_t a;
    asm("{ .reg .u64 t; cvta.to.shared.u64 t, %1; cvt.u32.u64 %0, t; }" : "=r"(a) : "l"(p));
    return a;
}
#define CP16(dst, src) \
    asm volatile("cp.async.cg.shared.global [%0], [%1], 16;" :: "r"(dst), "l"(src))
#define CP_COMMIT() asm volatile("cp.async.commit_group;" ::: "memory")
#define CP_WAIT3()  asm volatile("cp.async.wait_group 3;" ::: "memory")
#define CP_WAIT0()  asm volatile("cp.async.wait_group 0;" ::: "memory")

// swizzled offset inside a tile with 64B rows: 16B chunk XOR'ed by row bits
__device__ __forceinline__ uint32_t swz(int row, int c) {
    return (uint32_t)(row * 64 + ((c ^ ((row >> 1) & 3)) << 4));
}

__device__ __forceinline__ void ldsm4(uint32_t* r, uint32_t addr) {
    asm volatile("ldmatrix.sync.aligned.m8n8.x4.shared.b16 {%0,%1,%2,%3}, [%4];"
                 : "=r"(r[0]), "=r"(r[1]), "=r"(r[2]), "=r"(r[3]) : "r"(addr));
}

__device__ __forceinline__ void mma16816(float* d, const uint32_t* a, const uint32_t* b) {
    asm volatile(
        "mma.sync.aligned.m16n8k16.row.col.f32.f16.f16.f32 "
        "{%0,%1,%2,%3}, {%4,%5,%6,%7}, {%8,%9}, {%0,%1,%2,%3};"
        : "+f"(d[0]), "+f"(d[1]), "+f"(d[2]), "+f"(d[3])
        : "r"(a[0]), "r"(a[1]), "r"(a[2]), "r"(a[3]), "r"(b[0]), "r"(b[1]));
}

// A-style ldmatrix address: mat bit0 -> +8 rows, bit1 -> +k8 chunk
__device__ __forceinline__ uint32_t addrA(uint32_t tbase, int rowbase, int c0, int lid) {
    int m = lid >> 3, r8 = lid & 7;
    int row = rowbase + r8 + (m & 1) * 8;
    int ch  = c0 + (m >> 1);
    return tbase + swz(row, ch);
}
// B-style ldmatrix address: mat bit0 -> +k8 chunk, bit1 -> +8 rows
__device__ __forceinline__ uint32_t addrB(uint32_t tbase, int rowbase, int c0, int lid) {
    int m = lid >> 3, r8 = lid & 7;
    int row = rowbase + r8 + (m >> 1) * 8;
    int ch  = c0 + (m & 1);
    return tbase + swz(row, ch);
}

__device__ __forceinline__ uint32_t pack2h(float a, float b) {
    __half2 h = __floats2half2_rn(a, b);
    return *reinterpret_cast<uint32_t*>(&h);
}

// ---------------- pass 1: column stats partials + x -> fp16 (single read of x) ----------------
// 512 CTAs: 64-row groups x 2 column halves (measured optimum)
__global__ void stats_and_convx(const float* __restrict__ x) {
    const int bx  = blockIdx.x;
    const int tid = threadIdx.x;
    const int by  = bx >> 1;                       // 64-row group, 0..255
    const int c4  = (bx & 1) * 256 + tid;          // float4 column, 0..511
    const float4* p = (const float4*)x + (size_t)(by * 64) * (DK / 4) + c4;
    uint2* outp = (uint2*)((char*)g_Ah + (size_t)(by * 64) * 4096 + c4 * 8);
    float4 s  = make_float4(0.f, 0.f, 0.f, 0.f);
    float4 ss = make_float4(0.f, 0.f, 0.f, 0.f);
#pragma unroll 4
    for (int r = 0; r < 64; ++r) {
        float4 v = p[(size_t)r * (DK / 4)];
        s.x += v.x; s.y += v.y; s.z += v.z; s.w += v.w;
        ss.x += v.x * v.x; ss.y += v.y * v.y;
        ss.z += v.z * v.z; ss.w += v.w * v.w;
        uint2 h;
        h.x = pack2h(v.x, v.y);
        h.y = pack2h(v.z, v.w);
        outp[(size_t)r * (DK / 4)] = h;   // fp16 row = 4096 B = 512 uint2
    }
    *(float4*)&g_psum[by][c4 * 4] = s;
    *(float4*)&g_psq [by][c4 * 4] = ss;
}

__global__ void colstats_final(const float* __restrict__ gamma,
                               const float* __restrict__ beta) {
    int col = blockIdx.x * 256 + threadIdx.x;
    float s = 0.f, ss = 0.f;
#pragma unroll 8
    for (int c = 0; c < 256; ++c) { s += g_psum[c][col]; ss += g_psq[c][col]; }
    float mean = s / (float)NROWS;
    float var  = (ss - s * mean) / (float)(NROWS - 1);   // ddof=1 (torch.std)
    float inv  = rsqrtf(var + 1e-8f);
    float sc   = gamma[col] * inv;
    g_scale[col] = sc;
    g_shift[col] = beta[col] - mean * sc;
}

// ---------------- pass 2: W*scale -> fp16, plus folded bias c_j = b_j + dot(shift, W_j) ----------------
__global__ void convert_w_scaled(const float* __restrict__ w1,
                                 const float* __restrict__ w2,
                                 const float* __restrict__ b1v,
                                 const float* __restrict__ b2v) {
    __shared__ float red[16];
    const int j   = blockIdx.x;
    const int tid = threadIdx.x;
    const int k0  = tid * 8;                       // 8 columns per thread
    const float4* wp1 = (const float4*)(w1 + (size_t)j * DK + k0);
    const float4* wp2 = (const float4*)(w2 + (size_t)j * DK + k0);
    const float4* scp = (const float4*)(g_scale + k0);
    const float4* shp = (const float4*)(g_shift + k0);
    float4 a0 = wp1[0], a1 = wp1[1];
    float4 b0 = wp2[0], b1 = wp2[1];
    float4 s0 = scp[0], s1 = scp[1];
    float4 h0 = shp[0], h1 = shp[1];

    float w1s[8] = { a0.x*s0.x, a0.y*s0.y, a0.z*s0.z, a0.w*s0.w,
                     a1.x*s1.x, a1.y*s1.y, a1.z*s1.z, a1.w*s1.w };
    float w2s[8] = { b0.x*s0.x, b0.y*s0.y, b0.z*s0.z, b0.w*s0.w,
                     b1.x*s1.x, b1.y*s1.y, b1.z*s1.z, b1.w*s1.w };
    uint4 o1, o2;
    o1.x = pack2h(w1s[0], w1s[1]); o1.y = pack2h(w1s[2], w1s[3]);
    o1.z = pack2h(w1s[4], w1s[5]); o1.w = pack2h(w1s[6], w1s[7]);
    o2.x = pack2h(w2s[0], w2s[1]); o2.y = pack2h(w2s[2], w2s[3]);
    o2.z = pack2h(w2s[4], w2s[5]); o2.w = pack2h(w2s[6], w2s[7]);
    const size_t idx = (size_t)j * (DK / 8) + tid;
    g_W1h[idx] = o1;
    g_W2h[idx] = o2;

    float d1 = h0.x*a0.x + h0.y*a0.y + h0.z*a0.z + h0.w*a0.w
             + h1.x*a1.x + h1.y*a1.y + h1.z*a1.z + h1.w*a1.w;
    float d2 = h0.x*b0.x + h0.y*b0.y + h0.z*b0.z + h0.w*b0.w
             + h1.x*b1.x + h1.y*b1.y + h1.z*b1.z + h1.w*b1.w;
#pragma unroll
    for (int o = 16; o > 0; o >>= 1) {
        d1 += __shfl_down_sync(0xFFFFFFFF, d1, o);
        d2 += __shfl_down_sync(0xFFFFFFFF, d2, o);
    }
    const int wrp = tid >> 5, lid = tid & 31;
    if (lid == 0) { red[wrp] = d1; red[wrp + 8] = d2; }
    __syncthreads();
    if (tid == 0) {
        float c1 = 0.f, c2 = 0.f;
#pragma unroll
        for (int t = 0; t < 8; ++t) { c1 += red[t]; c2 += red[t + 8]; }
        g_c1[j] = c1 + b1v[j];
        g_c2[j] = c2 + b2v[j];
    }
}

__device__ __forceinline__ float clamp_small(float t) {
    const float EPS = 1e-12f;
    if (t >= 0.f && t <  EPS) return  EPS;
    if (t <  0.f && t > -EPS) return -EPS;
    return t;
}

// ---------------- fused dual GEMM (plain fp16 mma.sync, 8 warps x 32x32) ----------------
__global__ __launch_bounds__(256, 2)
void dual_gemm_mma(float* __restrict__ out) {
    extern __shared__ __align__(128) char smem[];
    const uint32_t sbase = smem_u32(smem);
    const uint32_t cbase = sbase + RING_B;         // 512B c1 + 512B c2 staging

    const int tid = threadIdx.x;
    const int lid = tid & 31;
    const int wid = tid >> 5;
    const int wm  = wid & 3;        // 4 warps along M
    const int wn  = wid >> 2;       // 2 warps along N

    // rasterize: 8 n-tiles per group, m fastest -> wave shares A rows & W cols in L2
    const int id  = blockIdx.x;
    const int grp = id >> 10;
    const int rem = id & 1023;
    const int m0  = (rem >> 3) * BM;
    const int n0  = ((grp << 3) | (rem & 7)) * BN;

    const char* srcA  = (const char*)g_Ah  + (size_t)m0 * 4096;
    const char* srcW1 = (const char*)g_W1h + (size_t)n0 * 4096;
    const char* srcW2 = (const char*)g_W2h + (size_t)n0 * 4096;

    const int arow0 = tid >> 2;        // 0..63, A covers 128 rows in two passes
    const int ac    = tid & 3;

    auto issueA = [&](int bi, int kb) {
        const uint32_t st = sbase + bi * STAGE_B;
#pragma unroll
        for (int j = 0; j < 2; ++j) {
            int row = arow0 + 64 * j;
            CP16(st + swz(row, ac), srcA + (size_t)row * 4096 + kb + ac * 16);
        }
    };
    auto issueW = [&](int bi, int kb) {
        const uint32_t st = sbase + bi * STAGE_B;
        uint32_t d = st + ATILE_B + swz(arow0, ac);
        const size_t off = (size_t)arow0 * 4096 + kb + ac * 16;
        CP16(d,           srcW1 + off);
        CP16(d + WTILE_B, srcW2 + off);
    };

    float acc1[2][4][4];
    float acc2[2][4][4];
#pragma unroll
    for (int mi = 0; mi < 2; ++mi)
#pragma unroll
        for (int ni = 0; ni < 4; ++ni)
#pragma unroll
            for (int j = 0; j < 4; ++j) { acc1[mi][ni][j] = 0.f; acc2[mi][ni][j] = 0.f; }

    // prologue: stage c1/c2 (64 threads x 16B covers both 512B vectors), then 4 ring stages
    if (tid < 32) {
        CP16(cbase + tid * 16,       (const char*)(g_c1 + n0) + tid * 16);
    } else if (tid < 64) {
        CP16(cbase + 512 + (tid - 32) * 16, (const char*)(g_c2 + n0) + (tid - 32) * 16);
    }
#pragma unroll
    for (int p = 0; p < 4; ++p) {
        issueA(p, p * 64);
        issueW(p, p * 64);
        CP_COMMIT();
    }

    for (int i = 0; i < NSTAGES_K; ++i) {
        CP_WAIT3();
        __syncthreads();   // orders compute(i-1) before writes into stage (i-1)%5 below
        const int   nb = (i + 4) % NST;
        const bool  pf = (i + 4 < NSTAGES_K);
        const uint32_t st  = sbase + (i % NST) * STAGE_B;
        const uint32_t stW = st + ATILE_B;

        if (pf) issueA(nb, (i + 4) * 64);

        // ---- ks = 0 ----
        {
            uint32_t ah[2][4];
            ldsm4(ah[0], addrA(st, wm * 32,      0, lid));
            ldsm4(ah[1], addrA(st, wm * 32 + 16, 0, lid));
            uint32_t w[2][8];
            ldsm4(&w[0][0], addrB(stW,           wn * 32,      0, lid));
            ldsm4(&w[0][4], addrB(stW,           wn * 32 + 16, 0, lid));
            ldsm4(&w[1][0], addrB(stW + WTILE_B, wn * 32,      0, lid));
            ldsm4(&w[1][4], addrB(stW + WTILE_B, wn * 32 + 16, 0, lid));
#pragma unroll
            for (int mi = 0; mi < 2; ++mi)
#pragma unroll
                for (int ni = 0; ni < 4; ++ni) {
                    mma16816(acc1[mi][ni], ah[mi], &w[0][ni * 2]);
                    mma16816(acc2[mi][ni], ah[mi], &w[1][ni * 2]);
                }
        }

        if (pf) issueW(nb, (i + 4) * 64);
        CP_COMMIT();

        // ---- ks = 1 ----
        {
            uint32_t ah[2][4];
            ldsm4(ah[0], addrA(st, wm * 32,      2, lid));
            ldsm4(ah[1], addrA(st, wm * 32 + 16, 2, lid));
            uint32_t w[2][8];
            ldsm4(&w[0][0], addrB(stW,           wn * 32,      2, lid));
            ldsm4(&w[0][4], addrB(stW,           wn * 32 + 16, 2, lid));
            ldsm4(&w[1][0], addrB(stW + WTILE_B, wn * 32,      2, lid));
            ldsm4(&w[1][4], addrB(stW + WTILE_B, wn * 32 + 16, 2, lid));
#pragma unroll
            for (int mi = 0; mi < 2; ++mi)
#pragma unroll
                for (int ni = 0; ni < 4; ++ni) {
                    mma16816(acc1[mi][ni], ah[mi], &w[0][ni * 2]);
                    mma16816(acc2[mi][ni], ah[mi], &w[1][ni * 2]);
                }
        }
        // no tail sync: head sync of next iteration provides the WAR ordering
    }
    CP_WAIT0();

    // epilogue: folded bias (from smem) + sigmoid + clamp + product
    const float* c1s = (const float*)(smem + RING_B);
    const float* c2s = (const float*)(smem + RING_B + 512);
#pragma unroll
    for (int mi = 0; mi < 2; ++mi) {
        const int mrow = m0 + wm * 32 + mi * 16 + (lid >> 2);
#pragma unroll
        for (int ni = 0; ni < 4; ++ni) {
            const int lc  = wn * 32 + ni * 8 + (lid & 3) * 2;   // 0..127 within tile
            const int col = n0 + lc;
            const float b1x = c1s[lc], b1y = c1s[lc + 1];
            const float b2x = c2s[lc], b2y = c2s[lc + 1];

            float h1, z, s;
            float2 r;
            h1 = clamp_small(acc1[mi][ni][0] + b1x);
            z  = acc2[mi][ni][0] + b2x;
            s  = clamp_small(1.0f / (1.0f + __expf(-z)));
            r.x = h1 * s;
            h1 = clamp_small(acc1[mi][ni][1] + b1y);
            z  = acc2[mi][ni][1] + b2y;
            s  = clamp_small(1.0f / (1.0f + __expf(-z)));
            r.y = h1 * s;
            *(float2*)(out + (size_t)mrow * DOUT + col) = r;

            h1 = clamp_small(acc1[mi][ni][2] + b1x);
            z  = acc2[mi][ni][2] + b2x;
            s  = clamp_small(1.0f / (1.0f + __expf(-z)));
            r.x = h1 * s;
            h1 = clamp_small(acc1[mi][ni][3] + b1y);
            z  = acc2[mi][ni][3] + b2y;
            s  = clamp_small(1.0f / (1.0f + __expf(-z)));
            r.y = h1 * s;
            *(float2*)(out + (size_t)(mrow + 8) * DOUT + col) = r;
        }
    }
}

// ---------------- launch ----------------
extern "C" void kernel_launch(void* const* d_in, const int* in_sizes, int n_in,
                              void* d_out, int out_size) {
    const float* x     = (const float*)d_in[0];
    const float* w1    = (const float*)d_in[1];
    const float* b1    = (const float*)d_in[2];
    const float* w2    = (const float*)d_in[3];
    const float* b2    = (const float*)d_in[4];
    const float* gamma = (const float*)d_in[5];
    const float* beta  = (const float*)d_in[6];
    float* out = (float*)d_out;

    cudaFuncSetAttribute(dual_gemm_mma, cudaFuncAttributeMaxDynamicSharedMemorySize,
                         SMEM_BYTES_G);

    stats_and_convx<<<512, 256>>>(x);
    colstats_final<<<DK / 256, 256>>>(gamma, beta);
    convert_w_scaled<<<DOUT, 256>>>(w1, w2, b1, b2);

    const int grid = (NROWS / BM) * (DOUT / BN);   // 4096
    dual_gemm_mma<<<grid, 256, SMEM_BYTES_G>>>(out);
}

// round 15
// speedup vs baseline: 1.0912x; 1.0391x over previous
#include <cuda_runtime.h>
#include <cuda_fp16.h>
#include <math.h>
#include <stdint.h>

#define NROWS 16384
#define DK    2048
#define DOUT  2048

// GEMM tiling: 128x64 CTA tile, 8 warps of 32x32, k32 stages, 6-stage ring
#define BM 128
#define BN 64
#define NST 6
#define ATILE_B (BM * 64)      // 8192 B  (128 rows x 32 fp16 = 64B rows)
#define WTILE_B (BN * 64)      // 4096 B
#define STAGE_B (ATILE_B + 2 * WTILE_B)   // 16384
#define RING_B  (NST * STAGE_B)           // 98304
#define SMEM_BYTES_G (RING_B + 1024)      // + c1/c2 staging
#define NSTAGES_K (DK / 32)    // 64

// ---------------- device scratch (no allocations allowed) ----------------
__device__ float g_psum[256][DK];
__device__ float g_psq [256][DK];
__device__ float g_scale[DK];
__device__ float g_shift[DK];
__device__ float g_c1[DOUT];            // folded: b1_j + dot(shift, W1_j)
__device__ float g_c2[DOUT];            // folded: b2_j + dot(shift, W2_j)

__device__ uint4 g_Ah [(size_t)NROWS * DK / 8];   // fp16 raw x, 64 MB
__device__ uint4 g_W1h[(size_t)DOUT * DK / 8];    // fp16 scaled weights, 8 MB each
__device__ uint4 g_W2h[(size_t)DOUT * DK / 8];

// ---------------- helpers ----------------
__device__ __forceinline__ uint32_t smem_u32(const void* p) {
    uint32_t a;
    asm("{ .reg .u64 t; cvta.to.shared.u64 t, %1; cvt.u32.u64 %0, t; }" : "=r"(a) : "l"(p));
    return a;
}
#define CP16(dst, src) \
    asm volatile("cp.async.cg.shared.global [%0], [%1], 16;" :: "r"(dst), "l"(src))
#define CP_COMMIT() asm volatile("cp.async.commit_group;" ::: "memory")
#define CP_WAIT4()  asm volatile("cp.async.wait_group 4;" ::: "memory")
#define CP_WAIT0()  asm volatile("cp.async.wait_group 0;" ::: "memory")

// swizzled offset inside a tile with 64B rows: 16B chunk XOR'ed by row bits
__device__ __forceinline__ uint32_t swz(int row, int c) {
    return (uint32_t)(row * 64 + ((c ^ ((row >> 1) & 3)) << 4));
}

__device__ __forceinline__ void ldsm4(uint32_t* r, uint32_t addr) {
    asm volatile("ldmatrix.sync.aligned.m8n8.x4.shared.b16 {%0,%1,%2,%3}, [%4];"
                 : "=r"(r[0]), "=r"(r[1]), "=r"(r[2]), "=r"(r[3]) : "r"(addr));
}

__device__ __forceinline__ void mma16816(float* d, const uint32_t* a, const uint32_t* b) {
    asm volatile(
        "mma.sync.aligned.m16n8k16.row.col.f32.f16.f16.f32 "
        "{%0,%1,%2,%3}, {%4,%5,%6,%7}, {%8,%9}, {%0,%1,%2,%3};"
        : "+f"(d[0]), "+f"(d[1]), "+f"(d[2]), "+f"(d[3])
        : "r"(a[0]), "r"(a[1]), "r"(a[2]), "r"(a[3]), "r"(b[0]), "r"(b[1]));
}

// A-style ldmatrix address: mat bit0 -> +8 rows, bit1 -> +k8 chunk
__device__ __forceinline__ uint32_t addrA(uint32_t tbase, int rowbase, int c0, int lid) {
    int m = lid >> 3, r8 = lid & 7;
    int row = rowbase + r8 + (m & 1) * 8;
    int ch  = c0 + (m >> 1);
    return tbase + swz(row, ch);
}
// B-style ldmatrix address: mat bit0 -> +k8 chunk, bit1 -> +8 rows
__device__ __forceinline__ uint32_t addrB(uint32_t tbase, int rowbase, int c0, int lid) {
    int m = lid >> 3, r8 = lid & 7;
    int row = rowbase + r8 + (m >> 1) * 8;
    int ch  = c0 + (m & 1);
    return tbase + swz(row, ch);
}

__device__ __forceinline__ uint32_t pack2h(float a, float b) {
    __half2 h = __floats2half2_rn(a, b);
    return *reinterpret_cast<uint32_t*>(&h);
}

// ---------------- pass 1: column stats partials + x -> fp16 (single read of x) ----------------
// 512 CTAs: 64-row groups x 2 column halves (measured optimum)
__global__ void stats_and_convx(const float* __restrict__ x) {
    const int bx  = blockIdx.x;
    const int tid = threadIdx.x;
    const int by  = bx >> 1;                       // 64-row group, 0..255
    const int c4  = (bx & 1) * 256 + tid;          // float4 column, 0..511
    const float4* p = (const float4*)x + (size_t)(by * 64) * (DK / 4) + c4;
    uint2* outp = (uint2*)((char*)g_Ah + (size_t)(by * 64) * 4096 + c4 * 8);
    float4 s  = make_float4(0.f, 0.f, 0.f, 0.f);
    float4 ss = make_float4(0.f, 0.f, 0.f, 0.f);
#pragma unroll 4
    for (int r = 0; r < 64; ++r) {
        float4 v = p[(size_t)r * (DK / 4)];
        s.x += v.x; s.y += v.y; s.z += v.z; s.w += v.w;
        ss.x += v.x * v.x; ss.y += v.y * v.y;
        ss.z += v.z * v.z; ss.w += v.w * v.w;
        uint2 h;
        h.x = pack2h(v.x, v.y);
        h.y = pack2h(v.z, v.w);
        outp[(size_t)r * (DK / 4)] = h;   // fp16 row = 4096 B = 512 uint2
    }
    *(float4*)&g_psum[by][c4 * 4] = s;
    *(float4*)&g_psq [by][c4 * 4] = ss;
}

// 64 CTAs x 256 threads: 8 threads per column, shfl-tree reduce (width 8)
__global__ void colstats_final(const float* __restrict__ gamma,
                               const float* __restrict__ beta) {
    const int tid = threadIdx.x;
    const int col = blockIdx.x * 32 + (tid >> 3);
    const int seg = tid & 7;                       // 32 partials per segment
    float s = 0.f, ss = 0.f;
#pragma unroll 8
    for (int c = seg * 32; c < seg * 32 + 32; ++c) {
        s  += g_psum[c][col];
        ss += g_psq [c][col];
    }
#pragma unroll
    for (int o = 4; o > 0; o >>= 1) {
        s  += __shfl_down_sync(0xFFFFFFFF, s,  o, 8);
        ss += __shfl_down_sync(0xFFFFFFFF, ss, o, 8);
    }
    if (seg == 0) {
        float mean = s / (float)NROWS;
        float var  = (ss - s * mean) / (float)(NROWS - 1);   // ddof=1 (torch.std)
        float inv  = rsqrtf(var + 1e-8f);
        float sc   = gamma[col] * inv;
        g_scale[col] = sc;
        g_shift[col] = beta[col] - mean * sc;
    }
}

// ---------------- pass 2: W*scale -> fp16, plus folded bias c_j = b_j + dot(shift, W_j) ----------------
__global__ void convert_w_scaled(const float* __restrict__ w1,
                                 const float* __restrict__ w2,
                                 const float* __restrict__ b1v,
                                 const float* __restrict__ b2v) {
    __shared__ float red[16];
    const int j   = blockIdx.x;
    const int tid = threadIdx.x;
    const int k0  = tid * 8;                       // 8 columns per thread
    const float4* wp1 = (const float4*)(w1 + (size_t)j * DK + k0);
    const float4* wp2 = (const float4*)(w2 + (size_t)j * DK + k0);
    const float4* scp = (const float4*)(g_scale + k0);
    const float4* shp = (const float4*)(g_shift + k0);
    float4 a0 = wp1[0], a1 = wp1[1];
    float4 b0 = wp2[0], b1 = wp2[1];
    float4 s0 = scp[0], s1 = scp[1];
    float4 h0 = shp[0], h1 = shp[1];

    float w1s[8] = { a0.x*s0.x, a0.y*s0.y, a0.z*s0.z, a0.w*s0.w,
                     a1.x*s1.x, a1.y*s1.y, a1.z*s1.z, a1.w*s1.w };
    float w2s[8] = { b0.x*s0.x, b0.y*s0.y, b0.z*s0.z, b0.w*s0.w,
                     b1.x*s1.x, b1.y*s1.y, b1.z*s1.z, b1.w*s1.w };
    uint4 o1, o2;
    o1.x = pack2h(w1s[0], w1s[1]); o1.y = pack2h(w1s[2], w1s[3]);
    o1.z = pack2h(w1s[4], w1s[5]); o1.w = pack2h(w1s[6], w1s[7]);
    o2.x = pack2h(w2s[0], w2s[1]); o2.y = pack2h(w2s[2], w2s[3]);
    o2.z = pack2h(w2s[4], w2s[5]); o2.w = pack2h(w2s[6], w2s[7]);
    const size_t idx = (size_t)j * (DK / 8) + tid;
    g_W1h[idx] = o1;
    g_W2h[idx] = o2;

    float d1 = h0.x*a0.x + h0.y*a0.y + h0.z*a0.z + h0.w*a0.w
             + h1.x*a1.x + h1.y*a1.y + h1.z*a1.z + h1.w*a1.w;
    float d2 = h0.x*b0.x + h0.y*b0.y + h0.z*b0.z + h0.w*b0.w
             + h1.x*b1.x + h1.y*b1.y + h1.z*b1.z + h1.w*b1.w;
#pragma unroll
    for (int o = 16; o > 0; o >>= 1) {
        d1 += __shfl_down_sync(0xFFFFFFFF, d1, o);
        d2 += __shfl_down_sync(0xFFFFFFFF, d2, o);
    }
    const int wrp = tid >> 5, lid = tid & 31;
    if (lid == 0) { red[wrp] = d1; red[wrp + 8] = d2; }
    __syncthreads();
    if (tid == 0) {
        float c1 = 0.f, c2 = 0.f;
#pragma unroll
        for (int t = 0; t < 8; ++t) { c1 += red[t]; c2 += red[t + 8]; }
        g_c1[j] = c1 + b1v[j];
        g_c2[j] = c2 + b2v[j];
    }
}

__device__ __forceinline__ float clamp_small(float t) {
    const float EPS = 1e-12f;
    if (t >= 0.f && t <  EPS) return  EPS;
    if (t <  0.f && t > -EPS) return -EPS;
    return t;
}

// ---------------- fused dual GEMM (plain fp16 mma.sync, 8 warps x 32x32) ----------------
__global__ __launch_bounds__(256, 2)
void dual_gemm_mma(float* __restrict__ out) {
    extern __shared__ __align__(128) char smem[];
    const uint32_t sbase = smem_u32(smem);
    const uint32_t cbase = sbase + RING_B;         // 512B c1 + 512B c2 staging

    const int tid = threadIdx.x;
    const int lid = tid & 31;
    const int wid = tid >> 5;
    const int wm  = wid & 3;        // 4 warps along M
    const int wn  = wid >> 2;       // 2 warps along N

    // rasterize: 8 n-tiles per group, m fastest -> wave shares A rows & W cols in L2
    const int id  = blockIdx.x;
    const int grp = id >> 10;
    const int rem = id & 1023;
    const int m0  = (rem >> 3) * BM;
    const int n0  = ((grp << 3) | (rem & 7)) * BN;

    const char* srcA  = (const char*)g_Ah  + (size_t)m0 * 4096;
    const char* srcW1 = (const char*)g_W1h + (size_t)n0 * 4096;
    const char* srcW2 = (const char*)g_W2h + (size_t)n0 * 4096;

    const int arow0 = tid >> 2;        // 0..63, A covers 128 rows in two passes
    const int ac    = tid & 3;

    auto issueA = [&](int bi, int kb) {
        const uint32_t st = sbase + bi * STAGE_B;
#pragma unroll
        for (int j = 0; j < 2; ++j) {
            int row = arow0 + 64 * j;
            CP16(st + swz(row, ac), srcA + (size_t)row * 4096 + kb + ac * 16);
        }
    };
    auto issueW = [&](int bi, int kb) {
        const uint32_t st = sbase + bi * STAGE_B;
        uint32_t d = st + ATILE_B + swz(arow0, ac);
        const size_t off = (size_t)arow0 * 4096 + kb + ac * 16;
        CP16(d,           srcW1 + off);
        CP16(d + WTILE_B, srcW2 + off);
    };

    float acc1[2][4][4];
    float acc2[2][4][4];
#pragma unroll
    for (int mi = 0; mi < 2; ++mi)
#pragma unroll
        for (int ni = 0; ni < 4; ++ni)
#pragma unroll
            for (int j = 0; j < 4; ++j) { acc1[mi][ni][j] = 0.f; acc2[mi][ni][j] = 0.f; }

    // prologue: stage c1/c2 (joins stage-0 commit group), then 5 ring stages in flight
    if (tid < 32) {
        CP16(cbase + tid * 16,       (const char*)(g_c1 + n0) + tid * 16);
    } else if (tid < 64) {
        CP16(cbase + 512 + (tid - 32) * 16, (const char*)(g_c2 + n0) + (tid - 32) * 16);
    }
#pragma unroll
    for (int p = 0; p < 5; ++p) {
        issueA(p, p * 64);
        issueW(p, p * 64);
        CP_COMMIT();
    }

    for (int i = 0; i < NSTAGES_K; ++i) {
        CP_WAIT4();
        __syncthreads();   // orders compute(i-1) before writes into stage (i-1)%6 below
        const int   nb = (i + 5) % NST;
        const bool  pf = (i + 5 < NSTAGES_K);
        const uint32_t st  = sbase + (i % NST) * STAGE_B;
        const uint32_t stW = st + ATILE_B;

        if (pf) issueA(nb, (i + 5) * 64);

        // ---- ks = 0 ----
        {
            uint32_t ah[2][4];
            ldsm4(ah[0], addrA(st, wm * 32,      0, lid));
            ldsm4(ah[1], addrA(st, wm * 32 + 16, 0, lid));
            uint32_t w[2][8];
            ldsm4(&w[0][0], addrB(stW,           wn * 32,      0, lid));
            ldsm4(&w[0][4], addrB(stW,           wn * 32 + 16, 0, lid));
            ldsm4(&w[1][0], addrB(stW + WTILE_B, wn * 32,      0, lid));
            ldsm4(&w[1][4], addrB(stW + WTILE_B, wn * 32 + 16, 0, lid));
#pragma unroll
            for (int mi = 0; mi < 2; ++mi)
#pragma unroll
                for (int ni = 0; ni < 4; ++ni) {
                    mma16816(acc1[mi][ni], ah[mi], &w[0][ni * 2]);
                    mma16816(acc2[mi][ni], ah[mi], &w[1][ni * 2]);
                }
        }

        if (pf) issueW(nb, (i + 5) * 64);
        CP_COMMIT();

        // ---- ks = 1 ----
        {
            uint32_t ah[2][4];
            ldsm4(ah[0], addrA(st, wm * 32,      2, lid));
            ldsm4(ah[1], addrA(st, wm * 32 + 16, 2, lid));
            uint32_t w[2][8];
            ldsm4(&w[0][0], addrB(stW,           wn * 32,      2, lid));
            ldsm4(&w[0][4], addrB(stW,           wn * 32 + 16, 2, lid));
            ldsm4(&w[1][0], addrB(stW + WTILE_B, wn * 32,      2, lid));
            ldsm4(&w[1][4], addrB(stW + WTILE_B, wn * 32 + 16, 2, lid));
#pragma unroll
            for (int mi = 0; mi < 2; ++mi)
#pragma unroll
                for (int ni = 0; ni < 4; ++ni) {
                    mma16816(acc1[mi][ni], ah[mi], &w[0][ni * 2]);
                    mma16816(acc2[mi][ni], ah[mi], &w[1][ni * 2]);
                }
        }
        // no tail sync: head sync of next iteration provides the WAR ordering
    }
    CP_WAIT0();

    // epilogue: folded bias (from smem) + sigmoid + clamp + product
    const float* c1s = (const float*)(smem + RING_B);
    const float* c2s = (const float*)(smem + RING_B + 512);
#pragma unroll
    for (int mi = 0; mi < 2; ++mi) {
        const int mrow = m0 + wm * 32 + mi * 16 + (lid >> 2);
#pragma unroll
        for (int ni = 0; ni < 4; ++ni) {
            const int lc  = wn * 32 + ni * 8 + (lid & 3) * 2;   // 0..127 within tile
            const int col = n0 + lc;
            const float b1x = c1s[lc], b1y = c1s[lc + 1];
            const float b2x = c2s[lc], b2y = c2s[lc + 1];

            float h1, z, s;
            float2 r;
            h1 = clamp_small(acc1[mi][ni][0] + b1x);
            z  = acc2[mi][ni][0] + b2x;
            s  = clamp_small(1.0f / (1.0f + __expf(-z)));
            r.x = h1 * s;
            h1 = clamp_small(acc1[mi][ni][1] + b1y);
            z  = acc2[mi][ni][1] + b2y;
            s  = clamp_small(1.0f / (1.0f + __expf(-z)));
            r.y = h1 * s;
            *(float2*)(out + (size_t)mrow * DOUT + col) = r;

            h1 = clamp_small(acc1[mi][ni][2] + b1x);
            z  = acc2[mi][ni][2] + b2x;
            s  = clamp_small(1.0f / (1.0f + __expf(-z)));
            r.x = h1 * s;
            h1 = clamp_small(acc1[mi][ni][3] + b1y);
            z  = acc2[mi][ni][3] + b2y;
            s  = clamp_small(1.0f / (1.0f + __expf(-z)));
            r.y = h1 * s;
            *(float2*)(out + (size_t)(mrow + 8) * DOUT + col) = r;
        }
    }
}

// ---------------- launch ----------------
extern "C" void kernel_launch(void* const* d_in, const int* in_sizes, int n_in,
                              void* d_out, int out_size) {
    const float* x     = (const float*)d_in[0];
    const float* w1    = (const float*)d_in[1];
    const float* b1    = (const float*)d_in[2];
    const float* w2    = (const float*)d_in[3];
    const float* b2    = (const float*)d_in[4];
    const float* gamma = (const float*)d_in[5];
    const float* beta  = (const float*)d_in[6];
    float* out = (float*)d_out;

    cudaFuncSetAttribute(dual_gemm_mma, cudaFuncAttributeMaxDynamicSharedMemorySize,
                         SMEM_BYTES_G);

    stats_and_convx<<<512, 256>>>(x);
    colstats_final<<<DK / 32, 256>>>(gamma, beta);
    convert_w_scaled<<<DOUT, 256>>>(w1, w2, b1, b2);

    const int grid = (NROWS / BM) * (DOUT / BN);   // 4096
    dual_gemm_mma<<<grid, 256, SMEM_BYTES_G>>>(out);
}